// round 8
// baseline (speedup 1.0000x reference)
#include <cuda_runtime.h>
#include <cuda_bf16.h>
#include <cstdint>
#include <cstring>

// ============================================================
// Problem constants
// ============================================================
static constexpr int SEQ   = 80;
static constexpr int EMB   = 100;
static constexpr int ROWS  = 32;    // batch rows per CTA
static constexpr int NCTA  = 128;   // 4096 / 32
static constexpr int THREADS = 256; // 8 warps: A = 0..3 (L1), B = 4..7 (L2)

// ---- Shared memory layout (bytes). Strides odd multiples of 16B ----
static constexpr int SX_W1 = 240;  // k=112 (x:100 + bias@100 + pad)
static constexpr int SX_U1 = 144;  // k=64
static constexpr int SX_W2 = 176;  // k=80 (h1:64 + bias@64 + pad)
static constexpr int SX_U2 = 144;  // k=64
static constexpr int OFF_W1 = 0;                           // 61440
static constexpr int OFF_U1 = OFF_W1 + 256 * SX_W1;        // 61440
static constexpr int OFF_W2 = OFF_U1 + 256 * SX_U1;        // 98304
static constexpr int OFF_U2 = OFF_W2 + 256 * SX_W2;        // 143360
static constexpr int OFF_X  = OFF_U2 + 256 * SX_U2;        // 180224: 2 x [32][240]
static constexpr int OFF_H1 = OFF_X  + 2 * ROWS * SX_W1;   // 195584: 2 x [32][176]
static constexpr int OFF_H2 = OFF_H1 + 2 * ROWS * SX_W2;   // 206848: 2 x [32][144]
static constexpr int OFF_WD = OFF_H2 + 2 * ROWS * SX_U2;   // 216064: 64 f32
static constexpr int OFF_BD = OFF_WD + 256;                // 216320
static constexpr int OFF_RED = OFF_BD + 16;                // 216336: [32][4] f32
static constexpr int SMEM_TOTAL = OFF_RED + 512;           // 216848
static constexpr int SMEM_ALLOC = 216960;

// ============================================================
// Helpers
// ============================================================
__device__ __forceinline__ uint32_t smem_to_u32(const void* smem_ptr) {
    uint32_t addr;
    asm("{ .reg .u64 tmp; cvta.to.shared.u64 tmp, %1; cvt.u32.u64 %0, tmp; }"
        : "=r"(addr) : "l"(smem_ptr));
    return addr;
}
__device__ __forceinline__ float tanhx(float x) {
    float y;
    asm("tanh.approx.f32 %0, %1;" : "=f"(y) : "f"(x));
    return y;
}
__device__ __forceinline__ float sigx(float x) {
    return fmaf(tanhx(0.5f * x), 0.5f, 0.5f);
}
__device__ __forceinline__ uint32_t packbf2(float lo, float hi) {
    __nv_bfloat162 v = __floats2bfloat162_rn(lo, hi);
    uint32_t u;
    memcpy(&u, &v, 4);
    return u;
}
__device__ __forceinline__ void ldsm_x4(uint32_t addr, uint32_t& r0, uint32_t& r1,
                                        uint32_t& r2, uint32_t& r3) {
    asm volatile("ldmatrix.sync.aligned.m8n8.x4.shared.b16 {%0,%1,%2,%3}, [%4];"
                 : "=r"(r0), "=r"(r1), "=r"(r2), "=r"(r3) : "r"(addr));
}
__device__ __forceinline__ void mma16816(float* d, uint32_t a0, uint32_t a1,
                                         uint32_t a2, uint32_t a3,
                                         uint32_t b0, uint32_t b1) {
    asm volatile(
        "mma.sync.aligned.m16n8k16.row.col.f32.bf16.bf16.f32 "
        "{%0,%1,%2,%3}, {%4,%5,%6,%7}, {%8,%9}, {%0,%1,%2,%3};"
        : "+f"(d[0]), "+f"(d[1]), "+f"(d[2]), "+f"(d[3])
        : "r"(a0), "r"(a1), "r"(a2), "r"(a3), "r"(b0), "r"(b1));
}

// Warp tile M=32 (all rows) x N=64 (4 gates x 16 units at UB).
// acc[gi*16 + mt*8 + nt*4 + rh*2 + uj]  (64 f32)
template <int KSTEPS>
__device__ __forceinline__ void do_term32(uint32_t aBase, int aStride,
                                          uint32_t bBase, int bStride,
                                          int UB, float* acc, int lane) {
    const int lrow = lane & 15;
    const int lk   = (lane >> 4) << 3;
#pragma unroll
    for (int ks = 0; ks < KSTEPS; ks++) {
        uint32_t a0, a1, a2, a3, a4, a5, a6, a7;
        ldsm_x4(aBase + lrow * aStride + (ks * 16 + lk) * 2, a0, a1, a2, a3);
        ldsm_x4(aBase + (16 + lrow) * aStride + (ks * 16 + lk) * 2, a4, a5, a6, a7);
#pragma unroll
        for (int gi = 0; gi < 4; gi++) {
            uint32_t r0, r1, r2, r3;
            ldsm_x4(bBase + (gi * 64 + UB + lrow) * bStride + (ks * 16 + lk) * 2,
                    r0, r1, r2, r3);
            mma16816(acc + gi * 16 + 0,  a0, a1, a2, a3, r0, r2);  // rows 0-15,  u UB..+7
            mma16816(acc + gi * 16 + 4,  a0, a1, a2, a3, r1, r3);  // rows 0-15,  u +8..15
            mma16816(acc + gi * 16 + 8,  a4, a5, a6, a7, r0, r2);  // rows 16-31
            mma16816(acc + gi * 16 + 12, a4, a5, a6, a7, r1, r3);
        }
    }
}

// Gate epilogue for the M=32 x (16-unit) warp tile.
__device__ __forceinline__ void epilogue32(const float* acc, float* c,
                                           uint32_t hBase, int hStride,
                                           int UB, int lane,
                                           const float* wd_s, float* pr) {
    const int g = lane >> 2, tg = lane & 3;
#pragma unroll
    for (int mt = 0; mt < 2; mt++)
#pragma unroll
    for (int nt = 0; nt < 2; nt++)
#pragma unroll
    for (int rh = 0; rh < 2; rh++) {
        float hv[2];
#pragma unroll
        for (int uj = 0; uj < 2; uj++) {
            const int ai = mt * 8 + nt * 4 + rh * 2 + uj;
            float zi = acc[ai], zf = acc[16 + ai];
            float zg = acc[32 + ai], zo = acc[48 + ai];
            float cc = sigx(zf) * c[ai] + sigx(zi) * tanhx(zg);
            c[ai] = cc;
            hv[uj] = sigx(zo) * tanhx(cc);
        }
        const int row = mt * 16 + rh * 8 + g;
        const int u   = UB + nt * 8 + 2 * tg;
        uint32_t pk = packbf2(hv[0], hv[1]);
        asm volatile("st.shared.b32 [%0], %1;"
                     :: "r"(hBase + row * hStride + u * 2), "r"(pk));
        if (wd_s) pr[mt * 2 + rh] += hv[0] * wd_s[u] + hv[1] * wd_s[u + 1];
    }
}

// x embedding gather: 4 threads per row (seg 0..3), 7 float4 max per thread.
__device__ __forceinline__ void gather_regs(const int* __restrict__ tokens,
                                            const float* __restrict__ emb,
                                            int grow, int t, int seg, float4* v) {
    int tok = tokens[grow * SEQ + t];
    const float4* ep = reinterpret_cast<const float4*>(emb + (size_t)tok * EMB);
#pragma unroll
    for (int j = 0; j < 6; j++) v[j] = ep[seg + 4 * j];
    if (seg == 0) v[6] = ep[24];
}
__device__ __forceinline__ void store_x(uint32_t xb, int seg, const float4* v) {
#pragma unroll
    for (int j = 0; j < 6; j++) {
        uint32_t lo = packbf2(v[j].x, v[j].y), hi = packbf2(v[j].z, v[j].w);
        asm volatile("st.shared.v2.b32 [%0], {%1,%2};"
                     :: "r"(xb + (seg + 4 * j) * 8), "r"(lo), "r"(hi));
    }
    if (seg == 0) {
        uint32_t lo = packbf2(v[6].x, v[6].y), hi = packbf2(v[6].z, v[6].w);
        asm volatile("st.shared.v2.b32 [%0], {%1,%2};"
                     :: "r"(xb + 24 * 8), "r"(lo), "r"(hi));
    }
}

// ============================================================
// Fused kernel: 1 CTA = 32 rows; group A runs L1(t+1) while group B runs L2(t)
// ============================================================
__global__ void __launch_bounds__(THREADS)
lstm_fused_kernel(const int* __restrict__ tokens,
                  const float* __restrict__ emb,
                  const float* __restrict__ W1, const float* __restrict__ U1,
                  const float* __restrict__ b1,
                  const float* __restrict__ W2, const float* __restrict__ U2,
                  const float* __restrict__ b2,
                  const float* __restrict__ Wd, const float* __restrict__ bd,
                  float* __restrict__ out) {
    extern __shared__ char smem[];
    const uint32_t sb = smem_to_u32(smem);
    const int tid  = threadIdx.x;
    const int wid  = tid >> 5;
    const int lane = tid & 31;
    const bool isA = (wid < 4);
    const int ug = wid & 3;
    const int UB = ug * 16;

    // ---- zero all smem ----
    for (int i = tid * 16; i < SMEM_TOTAL; i += THREADS * 16)
        *reinterpret_cast<uint4*>(smem + i) = make_uint4(0, 0, 0, 0);
    __syncthreads();

    // ---- stage weights: [n][k] bf16 (transposed), bias as extra k-column ----
    for (int i = tid; i < 256 * 101; i += THREADS) {      // W1t + b1@k=100
        int k = i / 256, n = i - k * 256;
        float v = (k < EMB) ? W1[k * 256 + n] : b1[n];
        *reinterpret_cast<__nv_bfloat16*>(smem + OFF_W1 + n * SX_W1 + k * 2) =
            __float2bfloat16(v);
    }
    for (int i = tid; i < 256 * 64; i += THREADS) {       // U1t
        int k = i >> 8, n = i & 255;
        *reinterpret_cast<__nv_bfloat16*>(smem + OFF_U1 + n * SX_U1 + k * 2) =
            __float2bfloat16(U1[k * 256 + n]);
    }
    for (int i = tid; i < 256 * 65; i += THREADS) {       // W2t + b2@k=64
        int k = i / 256, n = i - k * 256;
        float v = (k < 64) ? W2[k * 256 + n] : b2[n];
        *reinterpret_cast<__nv_bfloat16*>(smem + OFF_W2 + n * SX_W2 + k * 2) =
            __float2bfloat16(v);
    }
    for (int i = tid; i < 256 * 64; i += THREADS) {       // U2t
        int k = i >> 8, n = i & 255;
        *reinterpret_cast<__nv_bfloat16*>(smem + OFF_U2 + n * SX_U2 + k * 2) =
            __float2bfloat16(U2[k * 256 + n]);
    }
    if (tid < 64) *reinterpret_cast<float*>(smem + OFF_WD + 4 * tid) = Wd[tid];
    if (tid == 64) *reinterpret_cast<float*>(smem + OFF_BD) = bd[0];
    // static ones-columns in both parities: x[k=100] (b1), h1[k=64] (b2)
    if (tid < 2 * ROWS) {
        int b = tid >> 5, r = tid & 31;
        *reinterpret_cast<__nv_bfloat16*>(smem + OFF_X + b * ROWS * SX_W1 +
                                          r * SX_W1 + EMB * 2) = __float2bfloat16(1.0f);
        *reinterpret_cast<__nv_bfloat16*>(smem + OFF_H1 + b * ROWS * SX_W2 +
                                          r * SX_W2 + 64 * 2) = __float2bfloat16(1.0f);
    }

    // gather x(0) -> X[0] (threads 0..127), x(1) -> X[1] (threads 128..255)
    {
        int buf = tid >> 7, t7 = tid & 127;
        int xr = t7 >> 2, sg = t7 & 3;
        int gr = blockIdx.x * ROWS + xr;
        float4 v[7];
        gather_regs(tokens, emb, gr, buf, sg, v);
        store_x(sb + OFF_X + buf * ROWS * SX_W1 + xr * SX_W1, sg, v);
    }
    __syncthreads();

    const float* wd_s = reinterpret_cast<const float*>(smem + OFF_WD);
    float* red = reinterpret_cast<float*>(smem + OFF_RED);

    float acc[64], c[16], pr[4] = {0.f, 0.f, 0.f, 0.f};
#pragma unroll
    for (int q = 0; q < 16; q++) c[q] = 0.f;

    const int xrow = (tid & 127) >> 2, seg = tid & 3;
    const int grow = blockIdx.x * ROWS + xrow;

    // ---- prologue: L1(0) by group A (h1(-1)=0 so U1 term vanishes) ----
    if (isA) {
#pragma unroll
        for (int q = 0; q < 64; q++) acc[q] = 0.f;
        do_term32<7>(sb + OFF_X, SX_W1, sb + OFF_W1, SX_W1, UB, acc, lane);
        epilogue32(acc, c, sb + OFF_H1, SX_W2, UB, lane, nullptr, pr);  // h1(0)->H1[0]
    }
    __syncthreads();

    // ---- pipelined main loop: A computes L1(it+1), B computes L2(it) ----
#pragma unroll 1
    for (int it = 0; it < SEQ; it++) {
        if (isA) {
            if (it < SEQ - 1) {
                float4 v[7];
                const bool pf = (it + 2 < SEQ);
                if (pf) gather_regs(tokens, emb, grow, it + 2, seg, v);
#pragma unroll
                for (int q = 0; q < 64; q++) acc[q] = 0.f;
                do_term32<7>(sb + OFF_X + ((it + 1) & 1) * ROWS * SX_W1, SX_W1,
                             sb + OFF_W1, SX_W1, UB, acc, lane);
                do_term32<4>(sb + OFF_H1 + (it & 1) * ROWS * SX_W2, SX_W2,
                             sb + OFF_U1, SX_U1, UB, acc, lane);
                epilogue32(acc, c, sb + OFF_H1 + ((it + 1) & 1) * ROWS * SX_W2,
                           SX_W2, UB, lane, nullptr, pr);
                if (pf) store_x(sb + OFF_X + (it & 1) * ROWS * SX_W1 + xrow * SX_W1,
                                seg, v);
            }
        } else {
#pragma unroll
            for (int q = 0; q < 64; q++) acc[q] = 0.f;
            do_term32<5>(sb + OFF_H1 + (it & 1) * ROWS * SX_W2, SX_W2,
                         sb + OFF_W2, SX_W2, UB, acc, lane);
            do_term32<4>(sb + OFF_H2 + ((it + 1) & 1) * ROWS * SX_U2, SX_U2,
                         sb + OFF_U2, SX_U2, UB, acc, lane);
            epilogue32(acc, c, sb + OFF_H2 + (it & 1) * ROWS * SX_U2, SX_U2,
                       UB, lane, (it == SEQ - 1) ? wd_s : nullptr, pr);
        }
        __syncthreads();
    }

    // ---- dense head: out = sigmoid(h2(79) @ Wd + bd)  (pr lives in group B) ----
    if (!isA) {
#pragma unroll
        for (int rr = 0; rr < 4; rr++) {
            pr[rr] += __shfl_xor_sync(0xffffffffu, pr[rr], 1);
            pr[rr] += __shfl_xor_sync(0xffffffffu, pr[rr], 2);
        }
        if ((lane & 3) == 0) {
            int g = lane >> 2;
#pragma unroll
            for (int mt = 0; mt < 2; mt++)
#pragma unroll
            for (int rh = 0; rh < 2; rh++) {
                int row = mt * 16 + rh * 8 + g;
                red[row * 4 + ug] = pr[mt * 2 + rh];
            }
        }
    }
    __syncthreads();
    if (tid < ROWS) {
        float bdv = *reinterpret_cast<const float*>(smem + OFF_BD);
        float v = red[tid * 4 + 0] + red[tid * 4 + 1] +
                  red[tid * 4 + 2] + red[tid * 4 + 3] + bdv;
        out[blockIdx.x * ROWS + tid] = sigx(v);
    }
}

// ============================================================
// Launch
// ============================================================
extern "C" void kernel_launch(void* const* d_in, const int* in_sizes, int n_in,
                              void* d_out, int out_size) {
    const int*   tokens = (const int*)d_in[0];
    const float* emb    = (const float*)d_in[1];
    const float* W1     = (const float*)d_in[2];
    const float* U1     = (const float*)d_in[3];
    const float* b1     = (const float*)d_in[4];
    const float* W2     = (const float*)d_in[5];
    const float* U2     = (const float*)d_in[6];
    const float* b2     = (const float*)d_in[7];
    const float* Wd     = (const float*)d_in[8];
    const float* bd     = (const float*)d_in[9];
    float* out = (float*)d_out;

    cudaFuncSetAttribute(lstm_fused_kernel,
                         cudaFuncAttributeMaxDynamicSharedMemorySize, SMEM_ALLOC);
    lstm_fused_kernel<<<NCTA, THREADS, SMEM_ALLOC>>>(
        tokens, emb, W1, U1, b1, W2, U2, b2, Wd, bd, out);
}

// round 10
// speedup vs baseline: 1.2814x; 1.2814x over previous
#include <cuda_runtime.h>
#include <cuda_bf16.h>
#include <cstdint>
#include <cstring>

// ============================================================
// Problem constants
// ============================================================
static constexpr int SEQ   = 80;
static constexpr int EMB   = 100;
static constexpr int ROWS  = 32;    // batch rows per CTA
static constexpr int NCTA  = 128;   // 4096 / 32
static constexpr int THREADS = 256; // 8 warps: (rt 0..1) x (ug 0..3), M16 x N64 tiles

// ---- Shared memory layout (bytes). Strides odd multiples of 16B ----
static constexpr int SX_W1 = 240;  // k=112 (x:100 + bias@100 + pad)
static constexpr int SX_U1 = 144;  // k=64
static constexpr int SX_W2 = 176;  // k=80 (h1:64 + bias@64 + pad)
static constexpr int SX_U2 = 144;  // k=64
static constexpr int OFF_W1 = 0;                           // 61440
static constexpr int OFF_U1 = OFF_W1 + 256 * SX_W1;        // 61440
static constexpr int OFF_W2 = OFF_U1 + 256 * SX_U1;        // 98304
static constexpr int OFF_U2 = OFF_W2 + 256 * SX_W2;        // 143360
static constexpr int OFF_X  = OFF_U2 + 256 * SX_U2;        // 180224: 2 x [32][240]
static constexpr int OFF_H1 = OFF_X  + 2 * ROWS * SX_W1;   // 195584: 2 x [32][176]
static constexpr int OFF_H2 = OFF_H1 + 2 * ROWS * SX_W2;   // 206848: 2 x [32][144]
static constexpr int OFF_WD = OFF_H2 + 2 * ROWS * SX_U2;   // 216064: 64 f32
static constexpr int OFF_BD = OFF_WD + 256;                // 216320
static constexpr int OFF_RED = OFF_BD + 16;                // 216336: [32][4] f32
static constexpr int SMEM_TOTAL = OFF_RED + 512;           // 216848
static constexpr int SMEM_ALLOC = 216960;

// ============================================================
// Helpers
// ============================================================
__device__ __forceinline__ uint32_t smem_to_u32(const void* smem_ptr) {
    uint32_t addr;
    asm("{ .reg .u64 tmp; cvta.to.shared.u64 tmp, %1; cvt.u32.u64 %0, tmp; }"
        : "=r"(addr) : "l"(smem_ptr));
    return addr;
}
__device__ __forceinline__ float tanhx(float x) {
    float y;
    asm("tanh.approx.f32 %0, %1;" : "=f"(y) : "f"(x));
    return y;
}
__device__ __forceinline__ float sigx(float x) {
    return fmaf(tanhx(0.5f * x), 0.5f, 0.5f);
}
__device__ __forceinline__ uint32_t packbf2(float lo, float hi) {
    __nv_bfloat162 v = __floats2bfloat162_rn(lo, hi);
    uint32_t u;
    memcpy(&u, &v, 4);
    return u;
}
__device__ __forceinline__ void ldsm_x4(uint32_t addr, uint32_t& r0, uint32_t& r1,
                                        uint32_t& r2, uint32_t& r3) {
    asm volatile("ldmatrix.sync.aligned.m8n8.x4.shared.b16 {%0,%1,%2,%3}, [%4];"
                 : "=r"(r0), "=r"(r1), "=r"(r2), "=r"(r3) : "r"(addr));
}
__device__ __forceinline__ void mma16816(float* d, uint32_t a0, uint32_t a1,
                                         uint32_t a2, uint32_t a3,
                                         uint32_t b0, uint32_t b1) {
    asm volatile(
        "mma.sync.aligned.m16n8k16.row.col.f32.bf16.bf16.f32 "
        "{%0,%1,%2,%3}, {%4,%5,%6,%7}, {%8,%9}, {%0,%1,%2,%3};"
        : "+f"(d[0]), "+f"(d[1]), "+f"(d[2]), "+f"(d[3])
        : "r"(a0), "r"(a1), "r"(a2), "r"(a3), "r"(b0), "r"(b1));
}

// One GEMM term for warp tile M=16 (rows RB..RB+15) x N=64 (4 gates x 16 units).
// acc[gi*8 + nt*4 + j]
template <int KSTEPS>
__device__ __forceinline__ void do_term(uint32_t aBase, int aStride,
                                        uint32_t bBase, int bStride,
                                        int RB, int UB, float* acc, int lane) {
    const int lrow = lane & 15;
    const int lk   = (lane >> 4) << 3;
#pragma unroll
    for (int ks = 0; ks < KSTEPS; ks++) {
        uint32_t a0, a1, a2, a3;
        ldsm_x4(aBase + (RB + lrow) * aStride + (ks * 16 + lk) * 2, a0, a1, a2, a3);
#pragma unroll
        for (int gi = 0; gi < 4; gi++) {
            uint32_t r0, r1, r2, r3;
            ldsm_x4(bBase + (gi * 64 + UB + lrow) * bStride + (ks * 16 + lk) * 2,
                    r0, r1, r2, r3);
            mma16816(acc + gi * 8 + 0, a0, a1, a2, a3, r0, r2);
            mma16816(acc + gi * 8 + 4, a0, a1, a2, a3, r1, r3);
        }
    }
}

// Gate epilogue: acc (i,f,g,o) -> c update, h -> smem (bf16), optional dense dot.
__device__ __forceinline__ void epilogue(const float* acc, float* c,
                                         uint32_t hBase, int hStride,
                                         int RB, int UB, int lane,
                                         const float* wd_s, float* pr) {
    const int g = lane >> 2, tg = lane & 3;
#pragma unroll
    for (int nt = 0; nt < 2; nt++) {
#pragma unroll
        for (int rh = 0; rh < 2; rh++) {
            float hv[2];
#pragma unroll
            for (int uj = 0; uj < 2; uj++) {
                const int off = nt * 4 + rh * 2 + uj;
                float zi = acc[0 + off], zf = acc[8 + off];
                float zg = acc[16 + off], zo = acc[24 + off];
                float cc = sigx(zf) * c[off] + sigx(zi) * tanhx(zg);
                c[off] = cc;
                hv[uj] = sigx(zo) * tanhx(cc);
            }
            const int row = RB + rh * 8 + g;
            const int u   = UB + nt * 8 + 2 * tg;
            uint32_t pk = packbf2(hv[0], hv[1]);
            asm volatile("st.shared.b32 [%0], %1;"
                         :: "r"(hBase + row * hStride + u * 2), "r"(pk));
            if (wd_s) pr[rh] += hv[0] * wd_s[u] + hv[1] * wd_s[u + 1];
        }
    }
}

// x embedding gather (8 threads/row, seg 0..7)
__device__ __forceinline__ void gather_regs(const int* __restrict__ tokens,
                                            const float* __restrict__ emb,
                                            int grow, int t, int seg, float4* v) {
    int tok = tokens[grow * SEQ + t];
    const float4* ep = reinterpret_cast<const float4*>(emb + (size_t)tok * EMB);
    v[0] = ep[seg]; v[1] = ep[seg + 8]; v[2] = ep[seg + 16];
    if (seg == 0) v[3] = ep[24];
}
__device__ __forceinline__ void store_x(uint32_t xb, int seg, const float4* v) {
#pragma unroll
    for (int j = 0; j < 3; j++) {
        uint32_t lo = packbf2(v[j].x, v[j].y), hi = packbf2(v[j].z, v[j].w);
        asm volatile("st.shared.v2.b32 [%0], {%1,%2};"
                     :: "r"(xb + (seg + 8 * j) * 8), "r"(lo), "r"(hi));
    }
    if (seg == 0) {
        uint32_t lo = packbf2(v[3].x, v[3].y), hi = packbf2(v[3].z, v[3].w);
        asm volatile("st.shared.v2.b32 [%0], {%1,%2};"
                     :: "r"(xb + 24 * 8), "r"(lo), "r"(hi));
    }
}

// ============================================================
// Fused kernel: every warp computes L1(it+1) AND L2(it); 1 barrier per step
// ============================================================
__global__ void __launch_bounds__(THREADS)
lstm_fused_kernel(const int* __restrict__ tokens,
                  const float* __restrict__ emb,
                  const float* __restrict__ W1, const float* __restrict__ U1,
                  const float* __restrict__ b1,
                  const float* __restrict__ W2, const float* __restrict__ U2,
                  const float* __restrict__ b2,
                  const float* __restrict__ Wd, const float* __restrict__ bd,
                  float* __restrict__ out) {
    extern __shared__ char smem[];
    const uint32_t sb = smem_to_u32(smem);
    const int tid  = threadIdx.x;
    const int wid  = tid >> 5;
    const int lane = tid & 31;
    const int rt = wid >> 2, ug = wid & 3;
    const int RB = rt * 16, UB = ug * 16;

    // ---- zero all smem ----
    for (int i = tid * 16; i < SMEM_TOTAL; i += THREADS * 16)
        *reinterpret_cast<uint4*>(smem + i) = make_uint4(0, 0, 0, 0);
    __syncthreads();

    // ---- stage weights: [n][k] bf16 (transposed), bias as extra k-column ----
    for (int i = tid; i < 256 * 101; i += THREADS) {      // W1t + b1@k=100
        int k = i / 256, n = i - k * 256;
        float v = (k < EMB) ? W1[k * 256 + n] : b1[n];
        *reinterpret_cast<__nv_bfloat16*>(smem + OFF_W1 + n * SX_W1 + k * 2) =
            __float2bfloat16(v);
    }
    for (int i = tid; i < 256 * 64; i += THREADS) {       // U1t
        int k = i >> 8, n = i & 255;
        *reinterpret_cast<__nv_bfloat16*>(smem + OFF_U1 + n * SX_U1 + k * 2) =
            __float2bfloat16(U1[k * 256 + n]);
    }
    for (int i = tid; i < 256 * 65; i += THREADS) {       // W2t + b2@k=64
        int k = i / 256, n = i - k * 256;
        float v = (k < 64) ? W2[k * 256 + n] : b2[n];
        *reinterpret_cast<__nv_bfloat16*>(smem + OFF_W2 + n * SX_W2 + k * 2) =
            __float2bfloat16(v);
    }
    for (int i = tid; i < 256 * 64; i += THREADS) {       // U2t
        int k = i >> 8, n = i & 255;
        *reinterpret_cast<__nv_bfloat16*>(smem + OFF_U2 + n * SX_U2 + k * 2) =
            __float2bfloat16(U2[k * 256 + n]);
    }
    if (tid < 64) *reinterpret_cast<float*>(smem + OFF_WD + 4 * tid) = Wd[tid];
    if (tid == 64) *reinterpret_cast<float*>(smem + OFF_BD) = bd[0];
    // static ones-columns in both parities: x[k=100] (b1), h1[k=64] (b2)
    if (tid < 2 * ROWS) {
        int b = tid >> 5, r = tid & 31;
        *reinterpret_cast<__nv_bfloat16*>(smem + OFF_X + b * ROWS * SX_W1 +
                                          r * SX_W1 + EMB * 2) = __float2bfloat16(1.0f);
        *reinterpret_cast<__nv_bfloat16*>(smem + OFF_H1 + b * ROWS * SX_W2 +
                                          r * SX_W2 + 64 * 2) = __float2bfloat16(1.0f);
    }

    const int xrow = tid >> 3, seg = tid & 7;
    const int grow = blockIdx.x * ROWS + xrow;

    // gather x(0) -> X[0] and x(1) -> X[1]
    {
        float4 v[4];
        gather_regs(tokens, emb, grow, 0, seg, v);
        store_x(sb + OFF_X + xrow * SX_W1, seg, v);
        gather_regs(tokens, emb, grow, 1, seg, v);
        store_x(sb + OFF_X + ROWS * SX_W1 + xrow * SX_W1, seg, v);
    }
    __syncthreads();

    const float* wd_s = reinterpret_cast<const float*>(smem + OFF_WD);
    float* red = reinterpret_cast<float*>(smem + OFF_RED);

    float acc1[32], acc2[32], c1[8], c2[8], pr[2] = {0.f, 0.f};
#pragma unroll
    for (int q = 0; q < 8; q++) { c1[q] = 0.f; c2[q] = 0.f; }

    // ---- prologue: L1(0) (h1(-1)=0 so U1 term vanishes) -> h1(0) in H1[0] ----
#pragma unroll
    for (int q = 0; q < 32; q++) acc1[q] = 0.f;
    do_term<7>(sb + OFF_X, SX_W1, sb + OFF_W1, SX_W1, RB, UB, acc1, lane);
    epilogue(acc1, c1, sb + OFF_H1, SX_W2, RB, UB, lane, nullptr, pr);
    __syncthreads();

    // ---- main loop: each warp does L1(it+1) + L2(it); one barrier/step ----
    // Buffers at iter it:  X[(it+1)&1]=x(it+1), H1[it&1]=h1(it), H2[(it+1)&1]=h2(it-1)
#pragma unroll 1
    for (int it = 0; it < SEQ; it++) {
        const int pa = it & 1, pb = (it + 1) & 1;
        // prefetch x(it+2)
        float4 v[4];
        const bool pf = (it + 2 < SEQ);
        if (pf) gather_regs(tokens, emb, grow, it + 2, seg, v);

        const bool doL1 = (it < SEQ - 1);
#pragma unroll
        for (int q = 0; q < 32; q++) { acc1[q] = 0.f; acc2[q] = 0.f; }

        // two independent mma streams (interleaved by the scheduler)
        if (doL1)
            do_term<7>(sb + OFF_X + pb * ROWS * SX_W1, SX_W1,
                       sb + OFF_W1, SX_W1, RB, UB, acc1, lane);
        do_term<5>(sb + OFF_H1 + pa * ROWS * SX_W2, SX_W2,
                   sb + OFF_W2, SX_W2, RB, UB, acc2, lane);
        if (doL1)
            do_term<4>(sb + OFF_H1 + pa * ROWS * SX_W2, SX_W2,
                       sb + OFF_U1, SX_U1, RB, UB, acc1, lane);
        do_term<4>(sb + OFF_H2 + pb * ROWS * SX_U2, SX_U2,
                   sb + OFF_U2, SX_U2, RB, UB, acc2, lane);

        // epilogues: h1(it+1) -> H1[pb], h2(it) -> H2[pa]
        if (doL1)
            epilogue(acc1, c1, sb + OFF_H1 + pb * ROWS * SX_W2, SX_W2,
                     RB, UB, lane, nullptr, pr);
        epilogue(acc2, c2, sb + OFF_H2 + pa * ROWS * SX_U2, SX_U2,
                 RB, UB, lane, (it == SEQ - 1) ? wd_s : nullptr, pr);

        // store x(it+2) -> X[pa] (nobody reads X[pa] this iter)
        if (pf) store_x(sb + OFF_X + pa * ROWS * SX_W1 + xrow * SX_W1, seg, v);

        __syncthreads();
    }

    // ---- dense head: out = sigmoid(h2(79) @ Wd + bd) ----
#pragma unroll
    for (int rh = 0; rh < 2; rh++) {
        pr[rh] += __shfl_xor_sync(0xffffffffu, pr[rh], 1);
        pr[rh] += __shfl_xor_sync(0xffffffffu, pr[rh], 2);
    }
    if ((lane & 3) == 0) {
        int g = lane >> 2;
#pragma unroll
        for (int rh = 0; rh < 2; rh++)
            red[(RB + rh * 8 + g) * 4 + ug] = pr[rh];
    }
    __syncthreads();
    if (tid < ROWS) {
        float bdv = *reinterpret_cast<const float*>(smem + OFF_BD);
        float v = red[tid * 4 + 0] + red[tid * 4 + 1] +
                  red[tid * 4 + 2] + red[tid * 4 + 3] + bdv;
        out[blockIdx.x * ROWS + tid] = sigx(v);
    }
}

// ============================================================
// Launch
// ============================================================
extern "C" void kernel_launch(void* const* d_in, const int* in_sizes, int n_in,
                              void* d_out, int out_size) {
    const int*   tokens = (const int*)d_in[0];
    const float* emb    = (const float*)d_in[1];
    const float* W1     = (const float*)d_in[2];
    const float* U1     = (const float*)d_in[3];
    const float* b1     = (const float*)d_in[4];
    const float* W2     = (const float*)d_in[5];
    const float* U2     = (const float*)d_in[6];
    const float* b2     = (const float*)d_in[7];
    const float* Wd     = (const float*)d_in[8];
    const float* bd     = (const float*)d_in[9];
    float* out = (float*)d_out;

    cudaFuncSetAttribute(lstm_fused_kernel,
                         cudaFuncAttributeMaxDynamicSharedMemorySize, SMEM_ALLOC);
    lstm_fused_kernel<<<NCTA, THREADS, SMEM_ALLOC>>>(
        tokens, emb, W1, U1, b1, W2, U2, b2, Wd, bd, out);
}

// round 12
// speedup vs baseline: 1.3656x; 1.0657x over previous
#include <cuda_runtime.h>
#include <cuda_bf16.h>
#include <cstdint>
#include <cstring>

// ============================================================
// Problem constants
// ============================================================
static constexpr int SEQ   = 80;
static constexpr int EMB   = 100;
static constexpr int ROWS  = 32;    // batch rows per CTA
static constexpr int NCTA  = 128;   // 4096 / 32
static constexpr int THREADS = 512; // 16 warps: (rt 0..1) x (ug 0..7), M16 x N32 tiles

// ---- Shared memory layout (bytes). Strides odd multiples of 16B ----
static constexpr int SX_W1 = 240;  // k=112 (x:100 + bias@100 + pad)
static constexpr int SX_U1 = 144;  // k=64
static constexpr int SX_W2 = 176;  // k=80 (h1:64 + bias@64 + pad)
static constexpr int SX_U2 = 144;  // k=64
static constexpr int OFF_W1 = 0;                           // 61440
static constexpr int OFF_U1 = OFF_W1 + 256 * SX_W1;        // 61440
static constexpr int OFF_W2 = OFF_U1 + 256 * SX_U1;        // 98304
static constexpr int OFF_U2 = OFF_W2 + 256 * SX_W2;        // 143360
static constexpr int OFF_X  = OFF_U2 + 256 * SX_U2;        // 180224: 2 x [32][240]
static constexpr int OFF_H1 = OFF_X  + 2 * ROWS * SX_W1;   // 195584: 2 x [32][176]
static constexpr int OFF_H2 = OFF_H1 + 2 * ROWS * SX_W2;   // 206848: 2 x [32][144]
static constexpr int OFF_WD = OFF_H2 + 2 * ROWS * SX_U2;   // 216064: 64 f32
static constexpr int OFF_BD = OFF_WD + 256;                // 216320
static constexpr int OFF_RED = OFF_BD + 16;                // 216336: [32][8] f32
static constexpr int SMEM_TOTAL = OFF_RED + 1024;          // 217360
static constexpr int SMEM_ALLOC = 217472;

// ============================================================
// Helpers
// ============================================================
__device__ __forceinline__ uint32_t smem_to_u32(const void* smem_ptr) {
    uint32_t addr;
    asm("{ .reg .u64 tmp; cvta.to.shared.u64 tmp, %1; cvt.u32.u64 %0, tmp; }"
        : "=r"(addr) : "l"(smem_ptr));
    return addr;
}
__device__ __forceinline__ float tanhx(float x) {
    float y;
    asm("tanh.approx.f32 %0, %1;" : "=f"(y) : "f"(x));
    return y;
}
__device__ __forceinline__ float sigx(float x) {
    return fmaf(tanhx(0.5f * x), 0.5f, 0.5f);
}
__device__ __forceinline__ uint32_t packbf2(float lo, float hi) {
    __nv_bfloat162 v = __floats2bfloat162_rn(lo, hi);
    uint32_t u;
    memcpy(&u, &v, 4);
    return u;
}
__device__ __forceinline__ void ldsm_x4(uint32_t addr, uint32_t& r0, uint32_t& r1,
                                        uint32_t& r2, uint32_t& r3) {
    asm volatile("ldmatrix.sync.aligned.m8n8.x4.shared.b16 {%0,%1,%2,%3}, [%4];"
                 : "=r"(r0), "=r"(r1), "=r"(r2), "=r"(r3) : "r"(addr));
}
__device__ __forceinline__ void mma16816(float* d, uint32_t a0, uint32_t a1,
                                         uint32_t a2, uint32_t a3,
                                         uint32_t b0, uint32_t b1) {
    asm volatile(
        "mma.sync.aligned.m16n8k16.row.col.f32.bf16.bf16.f32 "
        "{%0,%1,%2,%3}, {%4,%5,%6,%7}, {%8,%9}, {%0,%1,%2,%3};"
        : "+f"(d[0]), "+f"(d[1]), "+f"(d[2]), "+f"(d[3])
        : "r"(a0), "r"(a1), "r"(a2), "r"(a3), "r"(b0), "r"(b1));
}

// One GEMM term for warp tile M=16 (rows RB..+15) x (4 gates x 8 units at UB).
// acc[gi*4 + rh*2 + uj]. Per kstep: 1 A-ldsm.x4, 2 B-ldsm.x4 (2 gates each), 4 mma.
template <int KSTEPS>
__device__ __forceinline__ void do_term(uint32_t aBase, int aStride,
                                        uint32_t bBase, int bStride,
                                        int RB, int UB, float* acc, int lane) {
    const int lrow = lane & 15;
    const int lk   = (lane >> 4) << 3;
    // B lane mapping: quad q = lane>>3; gate_in_pair = q>>1; k-half = q&1
    const int bq   = lane >> 3;
    const int brow = (bq >> 1) * 64 + UB + (lane & 7);
    const int bk   = (bq & 1) << 3;
#pragma unroll
    for (int ks = 0; ks < KSTEPS; ks++) {
        uint32_t a0, a1, a2, a3;
        ldsm_x4(aBase + (RB + lrow) * aStride + (ks * 16 + lk) * 2, a0, a1, a2, a3);
#pragma unroll
        for (int gp = 0; gp < 2; gp++) {  // gate pairs (0,1) and (2,3)
            uint32_t r0, r1, r2, r3;
            ldsm_x4(bBase + (gp * 128 + brow) * bStride + (ks * 16 + bk) * 2,
                    r0, r1, r2, r3);
            mma16816(acc + (2 * gp + 0) * 4, a0, a1, a2, a3, r0, r1);
            mma16816(acc + (2 * gp + 1) * 4, a0, a1, a2, a3, r2, r3);
        }
    }
}

// Gate epilogue for M16 x 8-unit tile: acc (i,f,g,o) -> c update, h -> smem.
__device__ __forceinline__ void epilogue(const float* acc, float* c,
                                         uint32_t hBase, int hStride,
                                         int RB, int UB, int lane,
                                         const float* wd_s, float* pr) {
    const int g = lane >> 2, tg = lane & 3;
#pragma unroll
    for (int rh = 0; rh < 2; rh++) {
        float hv[2];
#pragma unroll
        for (int uj = 0; uj < 2; uj++) {
            const int off = rh * 2 + uj;
            float zi = acc[0 + off], zf = acc[4 + off];
            float zg = acc[8 + off], zo = acc[12 + off];
            float cc = sigx(zf) * c[off] + sigx(zi) * tanhx(zg);
            c[off] = cc;
            hv[uj] = sigx(zo) * tanhx(cc);
        }
        const int row = RB + rh * 8 + g;
        const int u   = UB + 2 * tg;
        uint32_t pk = packbf2(hv[0], hv[1]);
        asm volatile("st.shared.b32 [%0], %1;"
                     :: "r"(hBase + row * hStride + u * 2), "r"(pk));
        if (wd_s) pr[rh] += hv[0] * wd_s[u] + hv[1] * wd_s[u + 1];
    }
}

// x embedding gather (8 threads/row, seg 0..7)
__device__ __forceinline__ void gather_regs(const int* __restrict__ tokens,
                                            const float* __restrict__ emb,
                                            int grow, int t, int seg, float4* v) {
    int tok = tokens[grow * SEQ + t];
    const float4* ep = reinterpret_cast<const float4*>(emb + (size_t)tok * EMB);
    v[0] = ep[seg]; v[1] = ep[seg + 8]; v[2] = ep[seg + 16];
    if (seg == 0) v[3] = ep[24];
}
__device__ __forceinline__ void store_x(uint32_t xb, int seg, const float4* v) {
#pragma unroll
    for (int j = 0; j < 3; j++) {
        uint32_t lo = packbf2(v[j].x, v[j].y), hi = packbf2(v[j].z, v[j].w);
        asm volatile("st.shared.v2.b32 [%0], {%1,%2};"
                     :: "r"(xb + (seg + 8 * j) * 8), "r"(lo), "r"(hi));
    }
    if (seg == 0) {
        uint32_t lo = packbf2(v[3].x, v[3].y), hi = packbf2(v[3].z, v[3].w);
        asm volatile("st.shared.v2.b32 [%0], {%1,%2};"
                     :: "r"(xb + 24 * 8), "r"(lo), "r"(hi));
    }
}

// ============================================================
// Fused kernel: 16 warps; every warp computes L1(it+1) AND L2(it); 1 barrier/step
// ============================================================
__global__ void __launch_bounds__(THREADS)
lstm_fused_kernel(const int* __restrict__ tokens,
                  const float* __restrict__ emb,
                  const float* __restrict__ W1, const float* __restrict__ U1,
                  const float* __restrict__ b1,
                  const float* __restrict__ W2, const float* __restrict__ U2,
                  const float* __restrict__ b2,
                  const float* __restrict__ Wd, const float* __restrict__ bd,
                  float* __restrict__ out) {
    extern __shared__ char smem[];
    const uint32_t sb = smem_to_u32(smem);
    const int tid  = threadIdx.x;
    const int wid  = tid >> 5;
    const int lane = tid & 31;
    const int rt = wid >> 3, ug = wid & 7;
    const int RB = rt * 16, UB = ug * 8;

    // ---- zero all smem ----
    for (int i = tid * 16; i < SMEM_TOTAL; i += THREADS * 16)
        *reinterpret_cast<uint4*>(smem + i) = make_uint4(0, 0, 0, 0);
    __syncthreads();

    // ---- stage weights: [n][k] bf16 (transposed), bias as extra k-column ----
    for (int i = tid; i < 256 * 101; i += THREADS) {      // W1t + b1@k=100
        int k = i / 256, n = i - k * 256;
        float v = (k < EMB) ? W1[k * 256 + n] : b1[n];
        *reinterpret_cast<__nv_bfloat16*>(smem + OFF_W1 + n * SX_W1 + k * 2) =
            __float2bfloat16(v);
    }
    for (int i = tid; i < 256 * 64; i += THREADS) {       // U1t
        int k = i >> 8, n = i & 255;
        *reinterpret_cast<__nv_bfloat16*>(smem + OFF_U1 + n * SX_U1 + k * 2) =
            __float2bfloat16(U1[k * 256 + n]);
    }
    for (int i = tid; i < 256 * 65; i += THREADS) {       // W2t + b2@k=64
        int k = i / 256, n = i - k * 256;
        float v = (k < 64) ? W2[k * 256 + n] : b2[n];
        *reinterpret_cast<__nv_bfloat16*>(smem + OFF_W2 + n * SX_W2 + k * 2) =
            __float2bfloat16(v);
    }
    for (int i = tid; i < 256 * 64; i += THREADS) {       // U2t
        int k = i >> 8, n = i & 255;
        *reinterpret_cast<__nv_bfloat16*>(smem + OFF_U2 + n * SX_U2 + k * 2) =
            __float2bfloat16(U2[k * 256 + n]);
    }
    if (tid < 64) *reinterpret_cast<float*>(smem + OFF_WD + 4 * tid) = Wd[tid];
    if (tid == 64) *reinterpret_cast<float*>(smem + OFF_BD) = bd[0];
    // static ones-columns in both parities: x[k=100] (b1), h1[k=64] (b2)
    if (tid < 2 * ROWS) {
        int b = tid >> 5, r = tid & 31;
        *reinterpret_cast<__nv_bfloat16*>(smem + OFF_X + b * ROWS * SX_W1 +
                                          r * SX_W1 + EMB * 2) = __float2bfloat16(1.0f);
        *reinterpret_cast<__nv_bfloat16*>(smem + OFF_H1 + b * ROWS * SX_W2 +
                                          r * SX_W2 + 64 * 2) = __float2bfloat16(1.0f);
    }

    // gather x(0)->X[0] (threads 0..255) and x(1)->X[1] (threads 256..511)
    {
        int buf = tid >> 8, t8 = tid & 255;
        int xr = t8 >> 3, sg = t8 & 7;
        int gr = blockIdx.x * ROWS + xr;
        float4 v[4];
        gather_regs(tokens, emb, gr, buf, sg, v);
        store_x(sb + OFF_X + buf * ROWS * SX_W1 + xr * SX_W1, sg, v);
    }
    __syncthreads();

    const float* wd_s = reinterpret_cast<const float*>(smem + OFF_WD);
    float* red = reinterpret_cast<float*>(smem + OFF_RED);

    float acc1[16], acc2[16], c1[4], c2[4], pr[2] = {0.f, 0.f};
#pragma unroll
    for (int q = 0; q < 4; q++) { c1[q] = 0.f; c2[q] = 0.f; }

    const int xrow = (tid & 255) >> 3, seg = tid & 7;
    const int grow = blockIdx.x * ROWS + xrow;
    const bool gth = (tid < 256);

    // ---- prologue: L1(0) (h1(-1)=0 so U1 term vanishes) -> h1(0) in H1[0] ----
#pragma unroll
    for (int q = 0; q < 16; q++) acc1[q] = 0.f;
    do_term<7>(sb + OFF_X, SX_W1, sb + OFF_W1, SX_W1, RB, UB, acc1, lane);
    epilogue(acc1, c1, sb + OFF_H1, SX_W2, RB, UB, lane, nullptr, pr);
    __syncthreads();

    // ---- main loop: each warp does L1(it+1) + L2(it); one barrier/step ----
    // Buffers at iter it: X[(it+1)&1]=x(it+1), H1[it&1]=h1(it), H2[(it+1)&1]=h2(it-1)
#pragma unroll 1
    for (int it = 0; it < SEQ; it++) {
        const int pa = it & 1, pb = (it + 1) & 1;
        float4 v[4];
        const bool pf = gth && (it + 2 < SEQ);
        if (pf) gather_regs(tokens, emb, grow, it + 2, seg, v);

        const bool doL1 = (it < SEQ - 1);
#pragma unroll
        for (int q = 0; q < 16; q++) { acc1[q] = 0.f; acc2[q] = 0.f; }

        if (doL1)
            do_term<7>(sb + OFF_X + pb * ROWS * SX_W1, SX_W1,
                       sb + OFF_W1, SX_W1, RB, UB, acc1, lane);
        do_term<5>(sb + OFF_H1 + pa * ROWS * SX_W2, SX_W2,
                   sb + OFF_W2, SX_W2, RB, UB, acc2, lane);
        if (doL1)
            do_term<4>(sb + OFF_H1 + pa * ROWS * SX_W2, SX_W2,
                       sb + OFF_U1, SX_U1, RB, UB, acc1, lane);
        do_term<4>(sb + OFF_H2 + pb * ROWS * SX_U2, SX_U2,
                   sb + OFF_U2, SX_U2, RB, UB, acc2, lane);

        if (doL1)
            epilogue(acc1, c1, sb + OFF_H1 + pb * ROWS * SX_W2, SX_W2,
                     RB, UB, lane, nullptr, pr);
        epilogue(acc2, c2, sb + OFF_H2 + pa * ROWS * SX_U2, SX_U2,
                 RB, UB, lane, (it == SEQ - 1) ? wd_s : nullptr, pr);

        if (pf) store_x(sb + OFF_X + pa * ROWS * SX_W1 + xrow * SX_W1, seg, v);

        __syncthreads();
    }

    // ---- dense head: out = sigmoid(h2(79) @ Wd + bd) ----
#pragma unroll
    for (int rh = 0; rh < 2; rh++) {
        pr[rh] += __shfl_xor_sync(0xffffffffu, pr[rh], 1);
        pr[rh] += __shfl_xor_sync(0xffffffffu, pr[rh], 2);
    }
    if ((lane & 3) == 0) {
        int g = lane >> 2;
#pragma unroll
        for (int rh = 0; rh < 2; rh++)
            red[(RB + rh * 8 + g) * 8 + ug] = pr[rh];
    }
    __syncthreads();
    if (tid < ROWS) {
        float bdv = *reinterpret_cast<const float*>(smem + OFF_BD);
        float v = bdv;
#pragma unroll
        for (int q = 0; q < 8; q++) v += red[tid * 8 + q];
        out[blockIdx.x * ROWS + tid] = sigx(v);
    }
}

// ============================================================
// Launch
// ============================================================
extern "C" void kernel_launch(void* const* d_in, const int* in_sizes, int n_in,
                              void* d_out, int out_size) {
    const int*   tokens = (const int*)d_in[0];
    const float* emb    = (const float*)d_in[1];
    const float* W1     = (const float*)d_in[2];
    const float* U1     = (const float*)d_in[3];
    const float* b1     = (const float*)d_in[4];
    const float* W2     = (const float*)d_in[5];
    const float* U2     = (const float*)d_in[6];
    const float* b2     = (const float*)d_in[7];
    const float* Wd     = (const float*)d_in[8];
    const float* bd     = (const float*)d_in[9];
    float* out = (float*)d_out;

    cudaFuncSetAttribute(lstm_fused_kernel,
                         cudaFuncAttributeMaxDynamicSharedMemorySize, SMEM_ALLOC);
    lstm_fused_kernel<<<NCTA, THREADS, SMEM_ALLOC>>>(
        tokens, emb, W1, U1, b1, W2, U2, b2, Wd, bd, out);
}